// round 7
// baseline (speedup 1.0000x reference)
#include <cuda_runtime.h>
#include <math.h>
#include <stdint.h>

#define BATCH 8
#define SEQ   2048
#define DIM   768
#define MTOT  (BATCH * SEQ)     // 16384

// ---- GEMM tile config (int8 mma.sync path, sm_103-safe) ----
#define BM 128
#define BN 128
#define BKB 64                        // K bytes per slab (=64 int8 elems)
#define ROWB 80                       // padded row bytes (64B data + 16B pad)
#define MATB 10240                    // 128 * ROWB, one plane (A1/A2/B1/B2)
#define STAGEB (4 * MATB)             // 40960
#define NSTAGES 4
#define GSMEM (NSTAGES * STAGEB)      // 163840

typedef signed char s8;

// ---------------- device scratch (allocation-free rule) ----------------
__device__ int   g_idx[BATCH * SEQ];
__device__ int   g_cnt[BATCH];
__device__ int   g_cntpad[BATCH];
__device__ s8    g_x1[MTOT * DIM], g_x2[MTOT * DIM];  __device__ float g_sx[MTOT];
__device__ s8    g_y1[MTOT * DIM], g_y2[MTOT * DIM];  __device__ float g_sy[MTOT];
__device__ s8    g_wq1[DIM * DIM], g_wq2[DIM * DIM];  __device__ float g_swq[DIM];
__device__ s8    g_wk1[DIM * DIM], g_wk2[DIM * DIM];  __device__ float g_swk[DIM];
__device__ s8    g_wv1[DIM * DIM], g_wv2[DIM * DIM];  __device__ float g_swv[DIM];
__device__ s8    g_wf1[DIM * DIM], g_wf2[DIM * DIM];  __device__ float g_swf[DIM];
__device__ s8    g_q1[MTOT * DIM], g_q2[MTOT * DIM];  __device__ float g_sq[MTOT];
__device__ s8    g_k1[MTOT * DIM], g_k2[MTOT * DIM];  __device__ float g_sk[MTOT];
__device__ s8    g_vt1[MTOT * DIM], g_vt2[MTOT * DIM]; __device__ float g_svt[BATCH * DIM];
__device__ unsigned int g_cmax[BATCH * DIM];
__device__ s8    g_m1[MTOT * DIM], g_m2[MTOT * DIM];  __device__ float g_sm[MTOT];
__device__ s8    g_p1[(size_t)BATCH * SEQ * SEQ];
__device__ s8    g_p2[(size_t)BATCH * SEQ * SEQ];
__device__ float g_sp[MTOT];
__device__ float g_s[(size_t)BATCH * SEQ * SEQ];       // fp32 scores
__device__ float g_tf[MTOT * DIM];                      // shared fp32 staging (Q/K/V/M)

// ---------------- PTX helpers ----------------
__device__ __forceinline__ uint32_t smem_u32(const void* p) {
    uint32_t a;
    asm("{ .reg .u64 t; cvta.to.shared.u64 t, %1; cvt.u32.u64 %0, t; }" : "=r"(a) : "l"(p));
    return a;
}
__device__ __forceinline__ void cp16(uint32_t s, const void* g) {
    asm volatile("cp.async.cg.shared.global [%0], [%1], 16;" :: "r"(s), "l"(g));
}
__device__ __forceinline__ void cp_commit() { asm volatile("cp.async.commit_group;" ::: "memory"); }
template <int N> __device__ __forceinline__ void cp_wait() {
    asm volatile("cp.async.wait_group %0;" :: "n"(N) : "memory");
}
__device__ __forceinline__ void ldmat_x4(uint32_t* r, uint32_t addr) {
    asm volatile("ldmatrix.sync.aligned.m8n8.x4.shared.b16 {%0,%1,%2,%3}, [%4];"
                 : "=r"(r[0]), "=r"(r[1]), "=r"(r[2]), "=r"(r[3]) : "r"(addr));
}
__device__ __forceinline__ void mma_s8(int* c, const uint32_t* a, uint32_t b0, uint32_t b1) {
    asm volatile(
        "mma.sync.aligned.m16n8k32.row.col.s32.s8.s8.s32 "
        "{%0,%1,%2,%3}, {%4,%5,%6,%7}, {%8,%9}, {%0,%1,%2,%3};"
        : "+r"(c[0]), "+r"(c[1]), "+r"(c[2]), "+r"(c[3])
        : "r"(a[0]), "r"(a[1]), "r"(a[2]), "r"(a[3]), "r"(b0), "r"(b1));
}
__device__ __forceinline__ void qdig(float q, s8& d1, s8& d2) {
    int a1 = __float2int_rn(q * 0.0078125f);
    a1 = max(-127, min(127, a1));
    int a2 = __float2int_rn(q - 128.f * (float)a1);
    a2 = max(-127, min(127, a2));
    d1 = (s8)a1; d2 = (s8)a2;
}

// ---------------------------------------------------------------------------
// int8 two-digit GEMM: C[m,n] = sA[m]*sB[n]*(16384*S1 + 128*S2) (+bias)
//   A planes: [M, Ap] bytes row-major; B planes: [N, Bp] bytes row-major.
//   mb/nb: per-batch M/N tile bounds; kb: per-batch K bound (bytes).
//   scat/scnt: epilogue row scatter with exact-count guard (fp32 out only).
// ---------------------------------------------------------------------------
__global__ __launch_bounds__(256, 1) void gemm_i8(
    const s8* __restrict__ A1, const s8* __restrict__ A2,
    const float* __restrict__ sA, long long lsA,
    const s8* __restrict__ B1, const s8* __restrict__ B2,
    const float* __restrict__ sB, long long lsB,
    const float* __restrict__ bias, float* __restrict__ C,
    int N, int K, int Ap, int Bp,
    long long strA, long long strB, long long strC,
    const int* __restrict__ mb, const int* __restrict__ nb, const int* __restrict__ kb,
    const int* __restrict__ scat, const int* __restrict__ scnt)
{
    extern __shared__ char smem[];
    const int tid = threadIdx.x;
    const int wid = tid >> 5;
    const int lane = tid & 31;
    const int bz = blockIdx.z;

    const int row0 = blockIdx.y * BM;
    const int col0 = blockIdx.x * BN;
    if (mb && row0 >= mb[bz]) return;
    if (nb && col0 >= nb[bz]) return;
    const int NS = (kb ? kb[bz] : K) / BKB;

    A1 += bz * strA; A2 += bz * strA;
    B1 += bz * strB; B2 += bz * strB;
    const long long coff = bz * strC;
    const uint32_t smem_base = smem_u32(smem);

    const int wm = (wid >> 2) * 64;
    const int wn = (wid & 3) * 32;

    int acc1[4][4][4], acc2[4][4][4];
#pragma unroll
    for (int i = 0; i < 4; i++)
#pragma unroll
        for (int j = 0; j < 4; j++)
#pragma unroll
            for (int t = 0; t < 4; t++) { acc1[i][j][t] = 0; acc2[i][j][t] = 0; }

    auto load_stage = [&](int st, int k0) {
        const uint32_t base = smem_base + (uint32_t)st * STAGEB;
#pragma unroll
        for (int i = 0; i < 2; i++) {              // A: 128 rows x 4 chunks of 16B
            int idx = tid + i * 256;
            int r = idx >> 2, c = idx & 3;
            uint32_t s = base + r * ROWB + c * 16;
            size_t g = (size_t)(row0 + r) * Ap + k0 + c * 16;
            cp16(s, A1 + g);
            cp16(s + MATB, A2 + g);
        }
#pragma unroll
        for (int i = 0; i < 2; i++) {              // B: 128 rows x 4 chunks
            int idx = tid + i * 256;
            int r = idx >> 2, c = idx & 3;
            uint32_t s = base + 2 * MATB + r * ROWB + c * 16;
            size_t g = (size_t)(col0 + r) * Bp + k0 + c * 16;
            cp16(s, B1 + g);
            cp16(s + MATB, B2 + g);
        }
        cp_commit();
    };

    const int lrow = lane & 15;
    const int lkh  = lane >> 4;
    const int brow = (lane & 7) + ((lane >> 4) << 3);
    const int bkh  = (lane >> 3) & 1;

    load_stage(0, 0);
    load_stage(1, BKB);
    load_stage(2, 2 * BKB);

    for (int s = 0; s < NS; s++) {
        if (s < NS - 2)       cp_wait<2>();
        else if (s == NS - 2) cp_wait<1>();
        else                  cp_wait<0>();
        __syncthreads();
        if (s + 3 < NS) load_stage((s + 3) & 3, (s + 3) * BKB);

        const uint32_t base = smem_base + (uint32_t)(s & 3) * STAGEB;
        const uint32_t aB = base;
        const uint32_t bB = base + 2 * MATB;

#pragma unroll
        for (int ks = 0; ks < 2; ks++) {           // two k32 windows per 64B slab
            uint32_t af1[4][4], af2[4][4];
#pragma unroll
            for (int im = 0; im < 4; im++) {
                uint32_t ad = aB + (uint32_t)((wm + im * 16 + lrow) * ROWB + ks * 32 + lkh * 16);
                ldmat_x4(af1[im], ad);
                ldmat_x4(af2[im], ad + MATB);
            }
            uint32_t bf1[2][4], bf2[2][4];
#pragma unroll
            for (int ib = 0; ib < 2; ib++) {
                uint32_t bd = bB + (uint32_t)((wn + ib * 16 + brow) * ROWB + ks * 32 + bkh * 16);
                ldmat_x4(bf1[ib], bd);
                ldmat_x4(bf2[ib], bd + MATB);
            }
#pragma unroll
            for (int im = 0; im < 4; im++) {
#pragma unroll
                for (int in4 = 0; in4 < 4; in4++) {
                    const int ib = in4 >> 1, hf = (in4 & 1) * 2;
                    mma_s8(acc1[im][in4], af1[im], bf1[ib][hf], bf1[ib][hf + 1]);
                    mma_s8(acc2[im][in4], af1[im], bf2[ib][hf], bf2[ib][hf + 1]);
                    mma_s8(acc2[im][in4], af2[im], bf1[ib][hf], bf1[ib][hf + 1]);
                }
            }
        }
        __syncthreads();
    }

    // ---- epilogue: fp32 recombine + scale + bias (+scatter) ----
    const float* sAb = sA + bz * lsA;
    const float* sBb = sB + bz * lsB;
    const int lane4 = lane >> 2;
    const int lanec = (lane & 3) * 2;
#pragma unroll
    for (int im = 0; im < 4; im++) {
        const int mc = row0 + wm + im * 16 + lane4;
        const float sa0 = sAb[mc], sa1 = sAb[mc + 8];
#pragma unroll
        for (int in4 = 0; in4 < 4; in4++) {
            const int nc = col0 + wn + in4 * 8 + lanec;
            const float sb0 = sBb[nc], sb1 = sBb[nc + 1];
            const float b0 = bias ? bias[nc] : 0.f;
            const float b1 = bias ? bias[nc + 1] : 0.f;
            float v00 = sa0 * sb0 * (16384.f * (float)acc1[im][in4][0] + 128.f * (float)acc2[im][in4][0]) + b0;
            float v01 = sa0 * sb1 * (16384.f * (float)acc1[im][in4][1] + 128.f * (float)acc2[im][in4][1]) + b1;
            float v10 = sa1 * sb0 * (16384.f * (float)acc1[im][in4][2] + 128.f * (float)acc2[im][in4][2]) + b0;
            float v11 = sa1 * sb1 * (16384.f * (float)acc1[im][in4][3] + 128.f * (float)acc2[im][in4][3]) + b1;
            if (scat) {
                const int c0 = scnt[bz];
                if (mc < c0) {
                    int o = scat[bz * SEQ + mc];
                    *(float2*)&C[coff + (long long)o * N + nc] = make_float2(v00, v01);
                }
                if (mc + 8 < c0) {
                    int o = scat[bz * SEQ + mc + 8];
                    *(float2*)&C[coff + (long long)o * N + nc] = make_float2(v10, v11);
                }
            } else {
                *(float2*)&C[coff + (long long)mc * N + nc]       = make_float2(v00, v01);
                *(float2*)&C[coff + (long long)(mc + 8) * N + nc] = make_float2(v10, v11);
            }
        }
    }
}

// ---------------------------------------------------------------------------
// mask compaction scan (unchanged)
// ---------------------------------------------------------------------------
__global__ __launch_bounds__(1024) void mask_scan_kernel(
    const int* __restrict__ mask, int* __restrict__ idx,
    int* __restrict__ cnt, int* __restrict__ cntpad)
{
    __shared__ int sa[2048], sb[2048];
    const int b = blockIdx.x;
    const int t = threadIdx.x;
    const int* m = mask + b * SEQ;
    sa[t] = (m[t] != 0);
    sa[t + 1024] = (m[t + 1024] != 0);
    __syncthreads();
    int* src = sa; int* dst = sb;
    for (int off = 1; off < 2048; off <<= 1) {
#pragma unroll
        for (int k = 0; k < 2; k++) {
            int i = t + k * 1024;
            dst[i] = src[i] + (i >= off ? src[i - off] : 0);
        }
        __syncthreads();
        int* tmp = src; src = dst; dst = tmp;
    }
#pragma unroll
    for (int k = 0; k < 2; k++) {
        int i = t + k * 1024;
        if (m[i] != 0) idx[b * SEQ + src[i] - 1] = i;
    }
    if (t == 0) {
        int c = src[2047];
        cnt[b] = c;
        cntpad[b] = (c + 127) & ~127;
    }
}

// ---------------------------------------------------------------------------
// Row quantize helpers: block of 192 threads handles one 768-elem row.
// ---------------------------------------------------------------------------
__device__ __forceinline__ float block_rowmax192(float v, float* red) {
    const int lid = threadIdx.x & 31, wid = threadIdx.x >> 5;
#pragma unroll
    for (int o = 16; o > 0; o >>= 1) v = fmaxf(v, __shfl_xor_sync(0xffffffffu, v, o));
    if (lid == 0) red[wid] = v;
    __syncthreads();
    float t = red[0];
#pragma unroll
    for (int w = 1; w < 6; w++) t = fmaxf(t, red[w]);
    return t;
}

__global__ __launch_bounds__(192) void gather_quant_kernel(
    const float* __restrict__ in, const int* __restrict__ idx,
    const int* __restrict__ cnt, const int* __restrict__ cntpad,
    s8* __restrict__ D1, s8* __restrict__ D2, float* __restrict__ S)
{
    __shared__ float red[6];
    const int b = blockIdx.y, j = blockIdx.x;
    if (j >= cntpad[b]) return;
    const int c = threadIdx.x * 4;
    float f[4] = {0.f, 0.f, 0.f, 0.f};
    if (j < cnt[b]) {
        int s = idx[b * SEQ + j];
        float4 v = *(const float4*)&in[((size_t)b * SEQ + s) * DIM + c];
        f[0] = v.x; f[1] = v.y; f[2] = v.z; f[3] = v.w;
    }
    float mx = fmaxf(fmaxf(fabsf(f[0]), fabsf(f[1])), fmaxf(fabsf(f[2]), fabsf(f[3])));
    float maxv = fmaxf(block_rowmax192(mx, red), 1e-30f);
    float inv = 16256.f / maxv;
    s8 d1[4], d2[4];
#pragma unroll
    for (int k = 0; k < 4; k++) qdig(f[k] * inv, d1[k], d2[k]);
    const size_t o = ((size_t)b * SEQ + j) * DIM + c;
    *(char4*)&D1[o] = *(char4*)d1;
    *(char4*)&D2[o] = *(char4*)d2;
    if (threadIdx.x == 0) S[b * SEQ + j] = maxv * (1.f / 16256.f);
}

__global__ __launch_bounds__(192) void rowquant_kernel(
    const float* __restrict__ X, const int* __restrict__ cntpad,
    s8* __restrict__ D1, s8* __restrict__ D2, float* __restrict__ S)
{
    __shared__ float red[6];
    const int b = blockIdx.y, j = blockIdx.x;
    if (j >= cntpad[b]) return;
    const int c = threadIdx.x * 4;
    float4 v = *(const float4*)&X[((size_t)b * SEQ + j) * DIM + c];
    float f[4] = {v.x, v.y, v.z, v.w};
    float mx = fmaxf(fmaxf(fabsf(f[0]), fabsf(f[1])), fmaxf(fabsf(f[2]), fabsf(f[3])));
    float maxv = fmaxf(block_rowmax192(mx, red), 1e-30f);
    float inv = 16256.f / maxv;
    s8 d1[4], d2[4];
#pragma unroll
    for (int k = 0; k < 4; k++) qdig(f[k] * inv, d1[k], d2[k]);
    const size_t o = ((size_t)b * SEQ + j) * DIM + c;
    *(char4*)&D1[o] = *(char4*)d1;
    *(char4*)&D2[o] = *(char4*)d2;
    if (threadIdx.x == 0) S[b * SEQ + j] = maxv * (1.f / 16256.f);
}

__global__ __launch_bounds__(192) void weight_quant_kernel(
    const float* __restrict__ w0, const float* __restrict__ w1,
    const float* __restrict__ w2, const float* __restrict__ w3,
    s8* __restrict__ a0, s8* __restrict__ b0, float* __restrict__ s0,
    s8* __restrict__ a1, s8* __restrict__ b1, float* __restrict__ s1,
    s8* __restrict__ a2, s8* __restrict__ b2, float* __restrict__ s2,
    s8* __restrict__ a3, s8* __restrict__ b3, float* __restrict__ s3)
{
    __shared__ float red[6];
    const int r = blockIdx.x;
    const float* w; s8 *D1, *D2; float* S;
    switch (blockIdx.y) {
        case 0:  w = w0; D1 = a0; D2 = b0; S = s0; break;
        case 1:  w = w1; D1 = a1; D2 = b1; S = s1; break;
        case 2:  w = w2; D1 = a2; D2 = b2; S = s2; break;
        default: w = w3; D1 = a3; D2 = b3; S = s3; break;
    }
    const int c = threadIdx.x * 4;
    float4 v = *(const float4*)&w[(size_t)r * DIM + c];
    float f[4] = {v.x, v.y, v.z, v.w};
    float mx = fmaxf(fmaxf(fabsf(f[0]), fabsf(f[1])), fmaxf(fabsf(f[2]), fabsf(f[3])));
    float maxv = fmaxf(block_rowmax192(mx, red), 1e-30f);
    float inv = 16256.f / maxv;
    s8 d1[4], d2[4];
#pragma unroll
    for (int k = 0; k < 4; k++) qdig(f[k] * inv, d1[k], d2[k]);
    const size_t o = (size_t)r * DIM + c;
    *(char4*)&D1[o] = *(char4*)d1;
    *(char4*)&D2[o] = *(char4*)d2;
    if (threadIdx.x == 0) S[r] = maxv * (1.f / 16256.f);
}

// ---------------------------------------------------------------------------
// V column-max (per d) + transpose-quantize to Vt planes [b][d][j]
// ---------------------------------------------------------------------------
__global__ __launch_bounds__(256) void cmax_fill_kernel(unsigned int* __restrict__ u) {
    u[blockIdx.x * 256 + threadIdx.x] = 0u;
}

__global__ __launch_bounds__(256) void colmax_kernel(
    const float* __restrict__ V, const int* __restrict__ cntpad,
    unsigned int* __restrict__ cmax)
{
    const int b = blockIdx.y;
    const int r0 = blockIdx.x * 128;
    const int cp = cntpad[b];
    const int tid = threadIdx.x;
    float m[3] = {0.f, 0.f, 0.f};
    for (int r = 0; r < 128; r++) {
        int j = r0 + r;
        if (j >= cp) break;
        const float* row = V + ((size_t)b * SEQ + j) * DIM;
#pragma unroll
        for (int i = 0; i < 3; i++) m[i] = fmaxf(m[i], fabsf(row[tid + i * 256]));
    }
#pragma unroll
    for (int i = 0; i < 3; i++)
        atomicMax(&cmax[b * DIM + tid + i * 256], __float_as_uint(m[i]));
}

__global__ __launch_bounds__(256) void vt_quant_kernel(
    const float* __restrict__ V, const int* __restrict__ cntpad,
    const unsigned int* __restrict__ cmax,
    s8* __restrict__ T1, s8* __restrict__ T2, float* __restrict__ S)
{
    __shared__ float tile[32][33];
    const int b = blockIdx.z;
    const int cp = cntpad[b];
    const int j0 = blockIdx.x * 32;
    if (j0 >= cp) return;
    const int d0 = blockIdx.y * 32;
    const int tx = threadIdx.x & 31, ty = threadIdx.x >> 5;
#pragma unroll
    for (int i = 0; i < 4; i++) {
        int j = j0 + ty + i * 8;
        tile[ty + i * 8][tx] = (j < cp) ? V[((size_t)b * SEQ + j) * DIM + d0 + tx] : 0.f;
    }
    __syncthreads();
#pragma unroll
    for (int i = 0; i < 4; i++) {
        int d = d0 + ty + i * 8;
        float maxv = fmaxf(__uint_as_float(cmax[b * DIM + d]), 1e-30f);
        float inv = 16256.f / maxv;
        float v = tile[tx][ty + i * 8];
        s8 d1, d2;
        qdig(v * inv, d1, d2);
        const size_t o = ((size_t)b * DIM + d) * SEQ + j0 + tx;
        T1[o] = d1; T2[o] = d2;
        if (tx == 0 && j0 == 0) S[b * DIM + d] = maxv * (1.f / 16256.f);
    }
}

// ---------------------------------------------------------------------------
// output bias prefill
// ---------------------------------------------------------------------------
__global__ __launch_bounds__(256) void bias_fill_kernel(
    float* __restrict__ out, const float* __restrict__ bias)
{
    int i = blockIdx.x * 256 + threadIdx.x;
    int c = (i * 4) % DIM;
    *(float4*)&out[(size_t)i * 4] = *(const float4*)&bias[c];
}

// ---------------------------------------------------------------------------
// compact softmax -> quantized P planes + per-row scale
// ---------------------------------------------------------------------------
__device__ __forceinline__ float warp_max(float v) {
#pragma unroll
    for (int o = 16; o > 0; o >>= 1) v = fmaxf(v, __shfl_xor_sync(0xffffffffu, v, o));
    return v;
}
__device__ __forceinline__ float warp_sum(float v) {
#pragma unroll
    for (int o = 16; o > 0; o >>= 1) v += __shfl_xor_sync(0xffffffffu, v, o);
    return v;
}

__global__ __launch_bounds__(256) void softmax_kernel(
    const float* __restrict__ S, const int* __restrict__ cnt, const int* __restrict__ cntpad,
    s8* __restrict__ P1, s8* __restrict__ P2, float* __restrict__ SP)
{
    const int b = blockIdx.x >> 11;
    const int j = blockIdx.x & (SEQ - 1);
    const int cp = cntpad[b];
    if (j >= cp) return;
    const int cn = cnt[b];
    const long long row = (long long)b * SEQ + j;
    const float* __restrict__ Srow = S + row * SEQ;

    __shared__ float red_max[8];
    __shared__ float red_sum[8];
    const int tid = threadIdx.x;
    const int wid = tid >> 5, lid = tid & 31;

    float vals[8];
    float m = -INFINITY;
#pragma unroll
    for (int i = 0; i < 8; i++) {
        int c = tid + i * 256;
        float s = (c < cn) ? Srow[c] : -INFINITY;
        vals[i] = s;
        m = fmaxf(m, s);
    }
    m = warp_max(m);
    if (lid == 0) red_max[wid] = m;
    __syncthreads();
    { float t = (lid < 8) ? red_max[lid] : -INFINITY; m = warp_max(t); }

    float sum = 0.f;
#pragma unroll
    for (int i = 0; i < 8; i++) {
        float e = __expf(vals[i] - m);
        vals[i] = e;
        sum += e;
    }
    sum = warp_sum(sum);
    if (lid == 0) red_sum[wid] = sum;
    __syncthreads();
    { float t = (lid < 8) ? red_sum[lid] : 0.f; sum = warp_sum(t); }

    const bool live = (j < cn);
    // P = (1/sum) * e;  store P = sp * (128*p1 + p2), sp = (1/sum)/16256, q = e*16256
#pragma unroll
    for (int i = 0; i < 8; i++) {
        int c = tid + i * 256;
        if (c < cp) {
            float q = (live && c < cn) ? vals[i] * 16256.f : 0.f;
            s8 d1, d2;
            qdig(q, d1, d2);
            P1[row * SEQ + c] = d1;
            P2[row * SEQ + c] = d2;
        }
    }
    if (tid == 0) SP[row] = live ? (1.f / sum) * (1.f / 16256.f) : 0.f;
}

// ---------------------------------------------------------------------------
extern "C" void kernel_launch(void* const* d_in, const int* in_sizes, int n_in,
                              void* d_out, int out_size)
{
    const float* query = (const float*)d_in[0];
    const float* value = (const float*)d_in[1];
    const int*   mask  = (const int*)  d_in[2];
    const float* q_w   = (const float*)d_in[3];
    const float* q_b   = (const float*)d_in[4];
    const float* k_w   = (const float*)d_in[5];
    const float* k_b   = (const float*)d_in[6];
    const float* v_w   = (const float*)d_in[7];
    const float* v_b   = (const float*)d_in[8];
    const float* fc_w  = (const float*)d_in[9];
    const float* fc_b  = (const float*)d_in[10];
    float* out = (float*)d_out;

    cudaFuncSetAttribute(gemm_i8, cudaFuncAttributeMaxDynamicSharedMemorySize, GSMEM);

    int *idxp, *cntp, *cpp;
    s8 *x1,*x2,*y1,*y2,*wq1,*wq2,*wk1,*wk2,*wv1,*wv2,*wf1,*wf2;
    s8 *q1,*q2,*k1,*k2,*vt1,*vt2,*m1,*m2,*p1,*p2;
    float *sx,*sy,*swq,*swk,*swv,*swf,*sq,*sk,*svt,*smm,*sp,*s_ptr,*tf;
    unsigned int* cmax;
    cudaGetSymbolAddress((void**)&idxp, g_idx);
    cudaGetSymbolAddress((void**)&cntp, g_cnt);
    cudaGetSymbolAddress((void**)&cpp, g_cntpad);
    cudaGetSymbolAddress((void**)&x1, g_x1);   cudaGetSymbolAddress((void**)&x2, g_x2);
    cudaGetSymbolAddress((void**)&y1, g_y1);   cudaGetSymbolAddress((void**)&y2, g_y2);
    cudaGetSymbolAddress((void**)&sx, g_sx);   cudaGetSymbolAddress((void**)&sy, g_sy);
    cudaGetSymbolAddress((void**)&wq1, g_wq1); cudaGetSymbolAddress((void**)&wq2, g_wq2);
    cudaGetSymbolAddress((void**)&wk1, g_wk1); cudaGetSymbolAddress((void**)&wk2, g_wk2);
    cudaGetSymbolAddress((void**)&wv1, g_wv1); cudaGetSymbolAddress((void**)&wv2, g_wv2);
    cudaGetSymbolAddress((void**)&wf1, g_wf1); cudaGetSymbolAddress((void**)&wf2, g_wf2);
    cudaGetSymbolAddress((void**)&swq, g_swq); cudaGetSymbolAddress((void**)&swk, g_swk);
    cudaGetSymbolAddress((void**)&swv, g_swv); cudaGetSymbolAddress((void**)&swf, g_swf);
    cudaGetSymbolAddress((void**)&q1, g_q1);   cudaGetSymbolAddress((void**)&q2, g_q2);
    cudaGetSymbolAddress((void**)&k1, g_k1);   cudaGetSymbolAddress((void**)&k2, g_k2);
    cudaGetSymbolAddress((void**)&sq, g_sq);   cudaGetSymbolAddress((void**)&sk, g_sk);
    cudaGetSymbolAddress((void**)&vt1, g_vt1); cudaGetSymbolAddress((void**)&vt2, g_vt2);
    cudaGetSymbolAddress((void**)&svt, g_svt); cudaGetSymbolAddress((void**)&cmax, g_cmax);
    cudaGetSymbolAddress((void**)&m1, g_m1);   cudaGetSymbolAddress((void**)&m2, g_m2);
    cudaGetSymbolAddress((void**)&smm, g_sm);
    cudaGetSymbolAddress((void**)&p1, g_p1);   cudaGetSymbolAddress((void**)&p2, g_p2);
    cudaGetSymbolAddress((void**)&sp, g_sp);
    cudaGetSymbolAddress((void**)&s_ptr, g_s);
    cudaGetSymbolAddress((void**)&tf, g_tf);

    const long long SD = (long long)SEQ * DIM;
    const long long SS = (long long)SEQ * SEQ;
    dim3 gproj(DIM / BN, SEQ / BM, BATCH);

    // 1) mask compaction
    mask_scan_kernel<<<BATCH, 1024>>>(mask, idxp, cntp, cpp);

    // 2) quantize inputs (gathered compact rows) + weights
    {
        dim3 gg(SEQ, BATCH);
        gather_quant_kernel<<<gg, 192>>>(query, idxp, cntp, cpp, x1, x2, sx);
        gather_quant_kernel<<<gg, 192>>>(value, idxp, cntp, cpp, y1, y2, sy);
        weight_quant_kernel<<<dim3(DIM, 4), 192>>>(q_w, k_w, v_w, fc_w,
                                                   wq1, wq2, swq, wk1, wk2, swk,
                                                   wv1, wv2, swv, wf1, wf2, swf);
    }

    // 3) output bias prefill (masked-query rows keep fc_b)
    bias_fill_kernel<<<MTOT * DIM / 4 / 256, 256>>>(out, fc_b);

    // 4) Q projection -> fp32 -> quant
    gemm_i8<<<gproj, 256, GSMEM>>>(x1, x2, sx, SEQ, wq1, wq2, swq, 0, q_b, tf,
                                   DIM, DIM, DIM, DIM, SD, 0, SD,
                                   cpp, nullptr, nullptr, nullptr, nullptr);
    rowquant_kernel<<<dim3(SEQ, BATCH), 192>>>(tf, cpp, q1, q2, sq);

    // 5) K projection -> fp32 -> quant
    gemm_i8<<<gproj, 256, GSMEM>>>(y1, y2, sy, SEQ, wk1, wk2, swk, 0, k_b, tf,
                                   DIM, DIM, DIM, DIM, SD, 0, SD,
                                   cpp, nullptr, nullptr, nullptr, nullptr);
    rowquant_kernel<<<dim3(SEQ, BATCH), 192>>>(tf, cpp, k1, k2, sk);

    // 6) V projection -> fp32 -> colmax -> transpose-quant
    gemm_i8<<<gproj, 256, GSMEM>>>(y1, y2, sy, SEQ, wv1, wv2, swv, 0, v_b, tf,
                                   DIM, DIM, DIM, DIM, SD, 0, SD,
                                   cpp, nullptr, nullptr, nullptr, nullptr);
    cmax_fill_kernel<<<BATCH * DIM / 256, 256>>>(cmax);
    colmax_kernel<<<dim3(SEQ / 128, BATCH), 256>>>(tf, cpp, cmax);
    vt_quant_kernel<<<dim3(SEQ / 32, DIM / 32, BATCH), 256>>>(tf, cpp, cmax, vt1, vt2, svt);

    // 7) scores S = Qq @ Kq^T
    {
        dim3 grid(SEQ / BN, SEQ / BM, BATCH);
        gemm_i8<<<grid, 256, GSMEM>>>(q1, q2, sq, SEQ, k1, k2, sk, SEQ, nullptr, s_ptr,
                                      SEQ, DIM, DIM, DIM, SD, SD, SS,
                                      cpp, cpp, nullptr, nullptr, nullptr);
    }

    // 8) softmax -> quantized P
    softmax_kernel<<<BATCH * SEQ, 256>>>(s_ptr, cntp, cpp, p1, p2, sp);

    // 9) merged M = P @ V  (B = Vt planes, K bound = cntpad)
    gemm_i8<<<gproj, 256, GSMEM>>>(p1, p2, sp, SEQ, vt1, vt2, svt, DIM, nullptr, tf,
                                   DIM, SEQ, SEQ, SEQ, SS, SD, SD,
                                   cpp, nullptr, cpp, nullptr, nullptr);
    rowquant_kernel<<<dim3(SEQ, BATCH), 192>>>(tf, cpp, m1, m2, smm);

    // 10) out = scatter(Mq @ Wf^T + fc_b)
    gemm_i8<<<gproj, 256, GSMEM>>>(m1, m2, smm, SEQ, wf1, wf2, swf, 0, fc_b, out,
                                   DIM, DIM, DIM, DIM, SD, 0, SD,
                                   cpp, nullptr, nullptr, idxp, cntp);
}

// round 10
// speedup vs baseline: 2.2751x; 2.2751x over previous
#include <cuda_runtime.h>
#include <cuda_fp16.h>
#include <math.h>
#include <stdint.h>

typedef __half f16;

#define BATCH 8
#define SEQ   2048
#define DIM   768
#define MTOT  (BATCH * SEQ)     // 16384

// ---- GEMM tile config (mma.sync path, sm_103-safe) ----
#define BM 128
#define BN 128
#define BK 32
#define ROWB 80                       // K-major padded row bytes (64B data + 16B pad)
#define ROWB_T 272                    // trans-B padded row bytes (256B data + 16B pad)
#define MATA_BYTES (128 * ROWB)       // 10240 (A hi or lo)
#define MATB_BYTES (128 * ROWB)       // 10240 (B K-major hi or lo)
#define MATBT_BYTES (32 * ROWB_T)     // 8704  (B trans hi or lo)
#define NSTAGES 4

// ---------------- device scratch (allocation-free rule) ----------------
__device__ int  g_idx[BATCH * SEQ];                      // compact -> orig position
__device__ int  g_cnt[BATCH];                            // exact unmasked count
__device__ int  g_cntpad[BATCH];                         // padded to 128
__device__ f16  g_xh[MTOT * DIM], g_xl[MTOT * DIM];     // query compact split
__device__ f16  g_yh[MTOT * DIM], g_yl[MTOT * DIM];     // value compact split
__device__ f16  g_wqh[DIM * DIM], g_wql[DIM * DIM];
__device__ f16  g_wkh[DIM * DIM], g_wkl[DIM * DIM];
__device__ f16  g_wvh[DIM * DIM], g_wvl[DIM * DIM];
__device__ f16  g_wfh[DIM * DIM], g_wfl[DIM * DIM];
__device__ f16  g_qh[MTOT * DIM], g_ql[MTOT * DIM];     // Q proj compact split
__device__ f16  g_kh[MTOT * DIM], g_kl[MTOT * DIM];     // K proj compact split
__device__ f16  g_vh[MTOT * DIM], g_vl[MTOT * DIM];     // V proj compact split
__device__ float g_s[(size_t)BATCH * SEQ * SEQ];         // scores fp32
__device__ f16  g_ph[(size_t)BATCH * SEQ * SEQ];         // probs split
__device__ f16  g_pl[(size_t)BATCH * SEQ * SEQ];
__device__ f16  g_mh[MTOT * DIM], g_ml[MTOT * DIM];     // merged compact split

// ---------------- PTX helpers (all plain-sm_103 legal) ----------------
__device__ __forceinline__ uint32_t smem_u32(const void* p) {
    uint32_t a;
    asm("{ .reg .u64 t; cvta.to.shared.u64 t, %1; cvt.u32.u64 %0, t; }" : "=r"(a) : "l"(p));
    return a;
}
__device__ __forceinline__ void cp16(uint32_t s, const void* g) {
    asm volatile("cp.async.cg.shared.global [%0], [%1], 16;" :: "r"(s), "l"(g));
}
__device__ __forceinline__ void cp_commit() { asm volatile("cp.async.commit_group;" ::: "memory"); }
template <int N> __device__ __forceinline__ void cp_wait() {
    asm volatile("cp.async.wait_group %0;" :: "n"(N) : "memory");
}
__device__ __forceinline__ void ldmat_x4(uint32_t* r, uint32_t addr) {
    asm volatile("ldmatrix.sync.aligned.m8n8.x4.shared.b16 {%0,%1,%2,%3}, [%4];"
                 : "=r"(r[0]), "=r"(r[1]), "=r"(r[2]), "=r"(r[3]) : "r"(addr));
}
__device__ __forceinline__ void ldmat_x4_t(uint32_t* r, uint32_t addr) {
    asm volatile("ldmatrix.sync.aligned.m8n8.x4.trans.shared.b16 {%0,%1,%2,%3}, [%4];"
                 : "=r"(r[0]), "=r"(r[1]), "=r"(r[2]), "=r"(r[3]) : "r"(addr));
}
// fp16 inputs, fp32 accumulator (main hi*hi term)
__device__ __forceinline__ void mma_f32acc(float* c, const uint32_t* a, uint32_t b0, uint32_t b1) {
    asm volatile(
        "mma.sync.aligned.m16n8k16.row.col.f32.f16.f16.f32 "
        "{%0,%1,%2,%3}, {%4,%5,%6,%7}, {%8,%9}, {%0,%1,%2,%3};"
        : "+f"(c[0]), "+f"(c[1]), "+f"(c[2]), "+f"(c[3])
        : "r"(a[0]), "r"(a[1]), "r"(a[2]), "r"(a[3]), "r"(b0), "r"(b1));
}
// fp16 inputs, fp16 accumulator (cross terms; magnitudes ~2^-11 of main)
__device__ __forceinline__ void mma_f16acc(uint32_t* c, const uint32_t* a, uint32_t b0, uint32_t b1) {
    asm volatile(
        "mma.sync.aligned.m16n8k16.row.col.f16.f16.f16.f16 "
        "{%0,%1}, {%2,%3,%4,%5}, {%6,%7}, {%0,%1};"
        : "+r"(c[0]), "+r"(c[1])
        : "r"(a[0]), "r"(a[1]), "r"(a[2]), "r"(a[3]), "r"(b0), "r"(b1));
}
__device__ __forceinline__ void fsplit(float v, f16& h, f16& l) {
    h = __float2half_rn(v);
    l = __float2half_rn(v - __half2float(h));
}

// ---------------------------------------------------------------------------
// mma.sync GEMM, 3-term fp16 split (hi*hi -> f32 acc; cross -> f16 acc):
//   BTRANS=0: B is [N,K] row-major  -> C = A @ B^T
//   BTRANS=1: B is [K,N] row-major  -> C = A @ B
// EPI=0: fp32 C (+bias, optional row scatter). EPI=1: f16 hi/lo split C (+bias).
// mb/nb/kb: per-batch device tile/K bounds.
// ---------------------------------------------------------------------------
template <int EPI, int BTRANS>
__global__ __launch_bounds__(256, 1) void gemm_mma(
    const f16* __restrict__ Agh, const f16* __restrict__ Agl,
    const f16* __restrict__ Bgh, const f16* __restrict__ Bgl,
    const float* __restrict__ bias,
    float* __restrict__ C, f16* __restrict__ Ch, f16* __restrict__ Cl,
    int M, int N, int K,
    long long sA, long long sB, long long sC,
    const int* __restrict__ mb, const int* __restrict__ nb, const int* __restrict__ kb,
    const int* __restrict__ scat, const int* __restrict__ scnt)
{
    constexpr uint32_t BPART = BTRANS ? MATBT_BYTES : MATB_BYTES;
    constexpr uint32_t STAGE = 2 * MATA_BYTES + 2 * BPART;

    extern __shared__ char smem[];
    const int tid = threadIdx.x;
    const int wid = tid >> 5;
    const int lane = tid & 31;
    const int bz = blockIdx.z;

    const int row0 = blockIdx.y * BM;
    const int col0 = blockIdx.x * BN;
    if (mb && row0 >= mb[bz]) return;
    if (nb && col0 >= nb[bz]) return;
    const int NS = (kb ? kb[bz] : K) / BK;

    Agh += bz * sA; Agl += bz * sA;
    Bgh += bz * sB; Bgl += bz * sB;
    const long long coff = bz * sC;
    const uint32_t smem_base = smem_u32(smem);

    const int wm = (wid >> 2) * 64;   // warp m offset in tile
    const int wn = (wid & 3) * 32;    // warp n offset in tile

    float acc[4][4][4];
    uint32_t accx[4][4][2];           // f16x2 cross accumulators
#pragma unroll
    for (int i = 0; i < 4; i++)
#pragma unroll
        for (int j = 0; j < 4; j++) {
#pragma unroll
            for (int t = 0; t < 4; t++) acc[i][j][t] = 0.f;
            accx[i][j][0] = 0u; accx[i][j][1] = 0u;
        }

    auto load_stage = [&](int st, int k0) {
        const uint32_t base = smem_base + (uint32_t)st * STAGE;
#pragma unroll
        for (int i = 0; i < 2; i++) {              // A: 128 rows x 4 chunks
            int idx = tid + i * 256;
            int r = idx >> 2, c = idx & 3;
            uint32_t s = base + r * ROWB + c * 16;
            size_t g = (size_t)(row0 + r) * K + k0 + c * 8;
            cp16(s, Agh + g);
            cp16(s + MATA_BYTES, Agl + g);
        }
        const uint32_t bb = base + 2 * MATA_BYTES;
        if (BTRANS) {
#pragma unroll
            for (int i = 0; i < 2; i++) {          // B: 32 k-rows x 16 chunks
                int idx = tid + i * 256;
                int r = idx >> 4, c = idx & 15;
                uint32_t s = bb + r * ROWB_T + c * 16;
                size_t g = (size_t)(k0 + r) * N + col0 + c * 8;
                cp16(s, Bgh + g);
                cp16(s + MATBT_BYTES, Bgl + g);
            }
        } else {
#pragma unroll
            for (int i = 0; i < 2; i++) {          // B: 128 n-rows x 4 chunks
                int idx = tid + i * 256;
                int r = idx >> 2, c = idx & 3;
                uint32_t s = bb + r * ROWB + c * 16;
                size_t g = (size_t)(col0 + r) * K + k0 + c * 8;
                cp16(s, Bgh + g);
                cp16(s + MATB_BYTES, Bgl + g);
            }
        }
        cp_commit();
    };

    const int lrow = lane & 15;
    const int lkh  = lane >> 4;
    const int brow = (lane & 7) + ((lane >> 4) << 3);
    const int bkh  = (lane >> 3) & 1;
    const int tkrow = lane & 15;
    const int tnoff = (lane >> 4) << 3;

    load_stage(0, 0);          // NS >= 4 in all uses (cntpad >= 128)
    load_stage(1, BK);
    load_stage(2, 2 * BK);

    for (int s = 0; s < NS; s++) {
        if (s < NS - 2)       cp_wait<2>();
        else if (s == NS - 2) cp_wait<1>();
        else                  cp_wait<0>();
        __syncthreads();
        if (s + 3 < NS) load_stage((s + 3) & 3, (s + 3) * BK);

        const uint32_t base = smem_base + (uint32_t)(s & 3) * STAGE;
        const uint32_t aB = base;
        const uint32_t bB = base + 2 * MATA_BYTES;

#pragma unroll
        for (int ks = 0; ks < 2; ks++) {
            uint32_t afh[4][4], afl[4][4];
#pragma unroll
            for (int im = 0; im < 4; im++) {
                uint32_t ad = aB + (uint32_t)((wm + im * 16 + lrow) * ROWB + ks * 32 + lkh * 16);
                ldmat_x4(afh[im], ad);
                ldmat_x4(afl[im], ad + MATA_BYTES);
            }
            uint32_t bfh[2][4], bfl[2][4];
#pragma unroll
            for (int ib = 0; ib < 2; ib++) {
                if (BTRANS) {
                    uint32_t bd = bB + (uint32_t)((ks * 16 + tkrow) * ROWB_T
                                                  + ((wn + ib * 16 + tnoff) << 1));
                    ldmat_x4_t(bfh[ib], bd);
                    ldmat_x4_t(bfl[ib], bd + MATBT_BYTES);
                } else {
                    uint32_t bd = bB + (uint32_t)((wn + ib * 16 + brow) * ROWB + ks * 32 + bkh * 16);
                    ldmat_x4(bfh[ib], bd);
                    ldmat_x4(bfl[ib], bd + MATB_BYTES);
                }
            }
#pragma unroll
            for (int im = 0; im < 4; im++) {
#pragma unroll
                for (int in4 = 0; in4 < 4; in4++) {
                    const int ib = in4 >> 1, hf = (in4 & 1) * 2;
                    mma_f32acc(acc[im][in4],  afh[im], bfh[ib][hf], bfh[ib][hf + 1]);
                    mma_f16acc(accx[im][in4], afh[im], bfl[ib][hf], bfl[ib][hf + 1]);
                    mma_f16acc(accx[im][in4], afl[im], bfh[ib][hf], bfh[ib][hf + 1]);
                }
            }
        }
        __syncthreads();
    }

    // ---- epilogue: combine f32 main + f16 cross ----
    const int lane4 = lane >> 2;
    const int lanec = (lane & 3) * 2;
#pragma unroll
    for (int im = 0; im < 4; im++) {
#pragma unroll
        for (int in4 = 0; in4 < 4; in4++) {
            const int mc = row0 + wm + im * 16 + lane4;
            const int nc = col0 + wn + in4 * 8 + lanec;
            float2 x01 = __half22float2(*(half2*)&accx[im][in4][0]);
            float2 x23 = __half22float2(*(half2*)&accx[im][in4][1]);
            float b0 = bias ? bias[nc] : 0.f;
            float b1 = bias ? bias[nc + 1] : 0.f;
            float v00 = acc[im][in4][0] + x01.x + b0, v01 = acc[im][in4][1] + x01.y + b1;
            float v10 = acc[im][in4][2] + x23.x + b0, v11 = acc[im][in4][3] + x23.y + b1;
            if (EPI == 0) {
                if (scat) {
                    const int c0 = scnt[bz];
                    if (mc < c0) {
                        int o = scat[bz * SEQ + mc];
                        *(float2*)&C[coff + (long long)o * N + nc] = make_float2(v00, v01);
                    }
                    if (mc + 8 < c0) {
                        int o = scat[bz * SEQ + mc + 8];
                        *(float2*)&C[coff + (long long)o * N + nc] = make_float2(v10, v11);
                    }
                } else {
                    *(float2*)&C[coff + (long long)mc * N + nc]       = make_float2(v00, v01);
                    *(float2*)&C[coff + (long long)(mc + 8) * N + nc] = make_float2(v10, v11);
                }
            } else {
                f16 h[2], l[2];
                fsplit(v00, h[0], l[0]); fsplit(v01, h[1], l[1]);
                *(uint32_t*)&Ch[coff + (long long)mc * N + nc] = *(uint32_t*)h;
                *(uint32_t*)&Cl[coff + (long long)mc * N + nc] = *(uint32_t*)l;
                fsplit(v10, h[0], l[0]); fsplit(v11, h[1], l[1]);
                *(uint32_t*)&Ch[coff + (long long)(mc + 8) * N + nc] = *(uint32_t*)h;
                *(uint32_t*)&Cl[coff + (long long)(mc + 8) * N + nc] = *(uint32_t*)l;
            }
        }
    }
}

// ---------------------------------------------------------------------------
// Per-batch mask compaction: deterministic inclusive scan.
// ---------------------------------------------------------------------------
__global__ __launch_bounds__(1024) void mask_scan_kernel(
    const int* __restrict__ mask, int* __restrict__ idx,
    int* __restrict__ cnt, int* __restrict__ cntpad)
{
    __shared__ int sa[2048], sb[2048];
    const int b = blockIdx.x;
    const int t = threadIdx.x;
    const int* m = mask + b * SEQ;
    sa[t] = (m[t] != 0);
    sa[t + 1024] = (m[t + 1024] != 0);
    __syncthreads();
    int* src = sa; int* dst = sb;
    for (int off = 1; off < 2048; off <<= 1) {
#pragma unroll
        for (int k = 0; k < 2; k++) {
            int i = t + k * 1024;
            dst[i] = src[i] + (i >= off ? src[i - off] : 0);
        }
        __syncthreads();
        int* tmp = src; src = dst; dst = tmp;
    }
#pragma unroll
    for (int k = 0; k < 2; k++) {
        int i = t + k * 1024;
        if (m[i] != 0) idx[b * SEQ + src[i] - 1] = i;
    }
    if (t == 0) {
        int c = src[2047];
        cnt[b] = c;
        cntpad[b] = (c + 127) & ~127;
    }
}

// ---------------------------------------------------------------------------
// Gather unmasked rows of fp32 input -> compact f16 hi/lo (zero padding rows)
// ---------------------------------------------------------------------------
__global__ __launch_bounds__(192) void gather_split_kernel(
    const float* __restrict__ in, const int* __restrict__ idx,
    const int* __restrict__ cnt, const int* __restrict__ cntpad,
    f16* __restrict__ h, f16* __restrict__ l)
{
    const int b = blockIdx.y, j = blockIdx.x;
    if (j >= cntpad[b]) return;
    const int c = threadIdx.x * 4;
    const size_t dsti = ((size_t)b * SEQ + j) * DIM + c;
    f16 hb[4], lb[4];
    if (j < cnt[b]) {
        int s = idx[b * SEQ + j];
        float4 v = *(const float4*)&in[((size_t)b * SEQ + s) * DIM + c];
        float f[4] = {v.x, v.y, v.z, v.w};
#pragma unroll
        for (int k = 0; k < 4; k++) fsplit(f[k], hb[k], lb[k]);
    } else {
#pragma unroll
        for (int k = 0; k < 4; k++) { hb[k] = __float2half_rn(0.f); lb[k] = hb[k]; }
    }
    *(uint2*)&h[dsti] = *(uint2*)hb;
    *(uint2*)&l[dsti] = *(uint2*)lb;
}

// ---------------------------------------------------------------------------
// Split 4 weight matrices in one launch
// ---------------------------------------------------------------------------
__global__ __launch_bounds__(256) void weight_split4_kernel(
    const float* __restrict__ w0, const float* __restrict__ w1,
    const float* __restrict__ w2, const float* __restrict__ w3,
    f16* __restrict__ h0, f16* __restrict__ l0, f16* __restrict__ h1, f16* __restrict__ l1,
    f16* __restrict__ h2, f16* __restrict__ l2, f16* __restrict__ h3, f16* __restrict__ l3)
{
    const int n4 = DIM * DIM / 4;
    int i = blockIdx.x * 256 + threadIdx.x;
    if (i >= n4) return;
    const float* w; f16 *h, *l;
    switch (blockIdx.y) {
        case 0: w = w0; h = h0; l = l0; break;
        case 1: w = w1; h = h1; l = l1; break;
        case 2: w = w2; h = h2; l = l2; break;
        default: w = w3; h = h3; l = l3; break;
    }
    float4 v = *(const float4*)&w[i * 4];
    float f[4] = {v.x, v.y, v.z, v.w};
    f16 hb[4], lb[4];
#pragma unroll
    for (int k = 0; k < 4; k++) fsplit(f[k], hb[k], lb[k]);
    *(uint2*)&h[i * 4] = *(uint2*)hb;
    *(uint2*)&l[i * 4] = *(uint2*)lb;
}

// ---------------------------------------------------------------------------
// Fill all output rows with fc bias (masked-query rows keep this value)
// ---------------------------------------------------------------------------
__global__ __launch_bounds__(256) void bias_fill_kernel(
    float* __restrict__ out, const float* __restrict__ bias)
{
    int i = blockIdx.x * 256 + threadIdx.x;
    int c = (i * 4) % DIM;
    *(float4*)&out[(size_t)i * 4] = *(const float4*)&bias[c];
}

// ---------------------------------------------------------------------------
// Compact softmax -> f16 hi/lo P
// ---------------------------------------------------------------------------
__device__ __forceinline__ float warp_max(float v) {
#pragma unroll
    for (int o = 16; o > 0; o >>= 1) v = fmaxf(v, __shfl_xor_sync(0xffffffffu, v, o));
    return v;
}
__device__ __forceinline__ float warp_sum(float v) {
#pragma unroll
    for (int o = 16; o > 0; o >>= 1) v += __shfl_xor_sync(0xffffffffu, v, o);
    return v;
}

__global__ __launch_bounds__(256) void softmax_kernel(
    const float* __restrict__ S, const int* __restrict__ cnt, const int* __restrict__ cntpad,
    f16* __restrict__ Ph, f16* __restrict__ Pl)
{
    const int b = blockIdx.x >> 11;
    const int j = blockIdx.x & (SEQ - 1);
    const int cp = cntpad[b];
    if (j >= cp) return;
    const int cn = cnt[b];
    const long long row = (long long)b * SEQ + j;
    const float* __restrict__ Srow = S + row * SEQ;

    __shared__ float red_max[8];
    __shared__ float red_sum[8];
    const int tid = threadIdx.x;
    const int wid = tid >> 5, lid = tid & 31;

    float vals[8];
    float m = -INFINITY;
#pragma unroll
    for (int i = 0; i < 8; i++) {
        int c = tid + i * 256;
        float s = (c < cn) ? Srow[c] : -INFINITY;
        vals[i] = s;
        m = fmaxf(m, s);
    }
    m = warp_max(m);
    if (lid == 0) red_max[wid] = m;
    __syncthreads();
    { float t = (lid < 8) ? red_max[lid] : -INFINITY; m = warp_max(t); }

    float sum = 0.f;
#pragma unroll
    for (int i = 0; i < 8; i++) {
        float e = __expf(vals[i] - m);
        vals[i] = e;
        sum += e;
    }
    sum = warp_sum(sum);
    if (lid == 0) red_sum[wid] = sum;
    __syncthreads();
    { float t = (lid < 8) ? red_sum[lid] : 0.f; sum = warp_sum(t); }

    const float scale = (j < cn) ? (1.f / sum) : 0.f;
#pragma unroll
    for (int i = 0; i < 8; i++) {
        int c = tid + i * 256;
        if (c < cp) {
            float p = (c < cn) ? vals[i] * scale : 0.f;
            f16 h, l;
            fsplit(p, h, l);
            Ph[row * SEQ + c] = h;
            Pl[row * SEQ + c] = l;
        }
    }
}

// ---------------------------------------------------------------------------
extern "C" void kernel_launch(void* const* d_in, const int* in_sizes, int n_in,
                              void* d_out, int out_size)
{
    const float* query = (const float*)d_in[0];
    const float* value = (const float*)d_in[1];
    const int*   mask  = (const int*)  d_in[2];
    const float* q_w   = (const float*)d_in[3];
    const float* q_b   = (const float*)d_in[4];
    const float* k_w   = (const float*)d_in[5];
    const float* k_b   = (const float*)d_in[6];
    const float* v_w   = (const float*)d_in[7];
    const float* v_b   = (const float*)d_in[8];
    const float* fc_w  = (const float*)d_in[9];
    const float* fc_b  = (const float*)d_in[10];
    float* out = (float*)d_out;

    const int SMEM_KM = NSTAGES * (2 * MATA_BYTES + 2 * MATB_BYTES);   // 163840
    const int SMEM_TR = NSTAGES * (2 * MATA_BYTES + 2 * MATBT_BYTES);  // 151552
    cudaFuncSetAttribute(gemm_mma<0,0>, cudaFuncAttributeMaxDynamicSharedMemorySize, SMEM_KM);
    cudaFuncSetAttribute(gemm_mma<1,0>, cudaFuncAttributeMaxDynamicSharedMemorySize, SMEM_KM);
    cudaFuncSetAttribute(gemm_mma<1,1>, cudaFuncAttributeMaxDynamicSharedMemorySize, SMEM_TR);

    int *idxp, *cntp, *cpp;
    f16 *xh, *xl, *yh, *yl, *wqh, *wql, *wkh, *wkl, *wvh, *wvl, *wfh, *wfl;
    f16 *qh, *ql, *kh, *kl, *vh, *vl, *ph, *pl, *mh, *ml;
    float *s_ptr;
    cudaGetSymbolAddress((void**)&idxp, g_idx);
    cudaGetSymbolAddress((void**)&cntp, g_cnt);
    cudaGetSymbolAddress((void**)&cpp, g_cntpad);
    cudaGetSymbolAddress((void**)&xh, g_xh);   cudaGetSymbolAddress((void**)&xl, g_xl);
    cudaGetSymbolAddress((void**)&yh, g_yh);   cudaGetSymbolAddress((void**)&yl, g_yl);
    cudaGetSymbolAddress((void**)&wqh, g_wqh); cudaGetSymbolAddress((void**)&wql, g_wql);
    cudaGetSymbolAddress((void**)&wkh, g_wkh); cudaGetSymbolAddress((void**)&wkl, g_wkl);
    cudaGetSymbolAddress((void**)&wvh, g_wvh); cudaGetSymbolAddress((void**)&wvl, g_wvl);
    cudaGetSymbolAddress((void**)&wfh, g_wfh); cudaGetSymbolAddress((void**)&wfl, g_wfl);
    cudaGetSymbolAddress((void**)&qh, g_qh);   cudaGetSymbolAddress((void**)&ql, g_ql);
    cudaGetSymbolAddress((void**)&kh, g_kh);   cudaGetSymbolAddress((void**)&kl, g_kl);
    cudaGetSymbolAddress((void**)&vh, g_vh);   cudaGetSymbolAddress((void**)&vl, g_vl);
    cudaGetSymbolAddress((void**)&s_ptr, g_s);
    cudaGetSymbolAddress((void**)&ph, g_ph);   cudaGetSymbolAddress((void**)&pl, g_pl);
    cudaGetSymbolAddress((void**)&mh, g_mh);   cudaGetSymbolAddress((void**)&ml, g_ml);

    // 1) mask compaction
    mask_scan_kernel<<<BATCH, 1024>>>(mask, idxp, cntp, cpp);

    // 2) gather + split inputs (compact rows); split weights (1 launch)
    {
        dim3 gg(SEQ, BATCH);
        gather_split_kernel<<<gg, 192>>>(query, idxp, cntp, cpp, xh, xl);
        gather_split_kernel<<<gg, 192>>>(value, idxp, cntp, cpp, yh, yl);
        weight_split4_kernel<<<dim3(576, 4), 256>>>(q_w, k_w, v_w, fc_w,
                                                    wqh, wql, wkh, wkl, wvh, wvl, wfh, wfl);
    }

    // 3) pre-fill output with fc bias (covers masked-query rows)
    bias_fill_kernel<<<MTOT * DIM / 4 / 256, 256>>>(out, fc_b);

    // 4) projections on compact rows (per-batch M bound)
    {
        dim3 grid(DIM / BN, SEQ / BM, BATCH);
        const long long sa = (long long)SEQ * DIM;
        gemm_mma<1,0><<<grid, 256, SMEM_KM>>>(xh, xl, wqh, wql, q_b, nullptr, qh, ql,
                                              SEQ, DIM, DIM, sa, 0, sa,
                                              cpp, nullptr, nullptr, nullptr, nullptr);
        gemm_mma<1,0><<<grid, 256, SMEM_KM>>>(yh, yl, wkh, wkl, k_b, nullptr, kh, kl,
                                              SEQ, DIM, DIM, sa, 0, sa,
                                              cpp, nullptr, nullptr, nullptr, nullptr);
        gemm_mma<1,0><<<grid, 256, SMEM_KM>>>(yh, yl, wvh, wvl, v_b, nullptr, vh, vl,
                                              SEQ, DIM, DIM, sa, 0, sa,
                                              cpp, nullptr, nullptr, nullptr, nullptr);
    }

    // 5) scores (compact M and N)
    {
        dim3 grid(SEQ / BN, SEQ / BM, BATCH);
        gemm_mma<0,0><<<grid, 256, SMEM_KM>>>(qh, ql, kh, kl, nullptr, s_ptr, nullptr, nullptr,
                                              SEQ, SEQ, DIM,
                                              (long long)SEQ * DIM, (long long)SEQ * DIM,
                                              (long long)SEQ * SEQ,
                                              cpp, cpp, nullptr, nullptr, nullptr);
    }

    // 6) compact softmax -> P hi/lo
    softmax_kernel<<<BATCH * SEQ, 256>>>(s_ptr, cntp, cpp, ph, pl);

    // 7) merged = P @ V (compact M and K; B=[K,N] via trans ldmatrix)
    {
        dim3 grid(DIM / BN, SEQ / BM, BATCH);
        gemm_mma<1,1><<<grid, 256, SMEM_TR>>>(ph, pl, vh, vl, nullptr, nullptr, mh, ml,
                                              SEQ, DIM, SEQ,
                                              (long long)SEQ * SEQ, (long long)SEQ * DIM,
                                              (long long)SEQ * DIM,
                                              cpp, nullptr, cpp, nullptr, nullptr);
    }

    // 8) out = scatter(fc(merged)) + fc_b (compact M, scatter rows)
    {
        dim3 grid(DIM / BN, SEQ / BM, BATCH);
        gemm_mma<0,0><<<grid, 256, SMEM_KM>>>(mh, ml, wfh, wfl, fc_b, out, nullptr, nullptr,
                                              SEQ, DIM, DIM,
                                              (long long)SEQ * DIM, 0, (long long)SEQ * DIM,
                                              cpp, nullptr, nullptr, idxp, cntp);
    }
}

// round 12
// speedup vs baseline: 2.5859x; 1.1366x over previous
#include <cuda_runtime.h>
#include <cuda_fp16.h>
#include <math.h>
#include <stdint.h>

typedef __half f16;

#define BATCH 8
#define SEQ   2048
#define DIM   768
#define MTOT  (BATCH * SEQ)     // 16384

// ---- GEMM tile config (mma.sync path, sm_103-safe) ----
#define BM 128
#define BN 128
#define BK 32
#define ROWB 80                       // K-major padded row bytes (64B data + 16B pad)
#define ROWB_T 272                    // trans-B padded row bytes (256B data + 16B pad)
#define MATA_BYTES (128 * ROWB)       // 10240 (A hi or lo)
#define MATB_BYTES (128 * ROWB)       // 10240 (B K-major hi or lo)
#define MATBT_BYTES (32 * ROWB_T)     // 8704  (B trans hi or lo)
#define NSTAGES 4

// ---------------- device scratch (allocation-free rule) ----------------
__device__ int  g_idx[BATCH * SEQ];                      // compact -> orig position
__device__ int  g_cnt[BATCH];                            // exact unmasked count
__device__ int  g_cntpad[BATCH];                         // padded to 128
__device__ f16  g_xh[MTOT * DIM], g_xl[MTOT * DIM];     // query compact split
__device__ f16  g_yh[MTOT * DIM], g_yl[MTOT * DIM];     // value compact split
__device__ f16  g_wqh[DIM * DIM], g_wql[DIM * DIM];
__device__ f16  g_wkh[DIM * DIM], g_wkl[DIM * DIM];
__device__ f16  g_wvh[DIM * DIM], g_wvl[DIM * DIM];
__device__ f16  g_wfh[DIM * DIM], g_wfl[DIM * DIM];
__device__ f16  g_qh[MTOT * DIM], g_ql[MTOT * DIM];     // Q proj compact split
__device__ f16  g_kh[MTOT * DIM], g_kl[MTOT * DIM];     // K proj compact split
__device__ f16  g_vh[MTOT * DIM], g_vl[MTOT * DIM];     // V proj compact split
__device__ float g_s[(size_t)BATCH * SEQ * SEQ];         // scores fp32
__device__ f16  g_ph[(size_t)BATCH * SEQ * SEQ];         // probs (hi only)
__device__ f16  g_mh[MTOT * DIM];                        // merged compact (hi only)

// ---------------- PTX helpers (all plain-sm_103 legal) ----------------
__device__ __forceinline__ uint32_t smem_u32(const void* p) {
    uint32_t a;
    asm("{ .reg .u64 t; cvta.to.shared.u64 t, %1; cvt.u32.u64 %0, t; }" : "=r"(a) : "l"(p));
    return a;
}
__device__ __forceinline__ void cp16(uint32_t s, const void* g) {
    asm volatile("cp.async.cg.shared.global [%0], [%1], 16;" :: "r"(s), "l"(g));
}
__device__ __forceinline__ void cp_commit() { asm volatile("cp.async.commit_group;" ::: "memory"); }
template <int N> __device__ __forceinline__ void cp_wait() {
    asm volatile("cp.async.wait_group %0;" :: "n"(N) : "memory");
}
__device__ __forceinline__ void ldmat_x4(uint32_t* r, uint32_t addr) {
    asm volatile("ldmatrix.sync.aligned.m8n8.x4.shared.b16 {%0,%1,%2,%3}, [%4];"
                 : "=r"(r[0]), "=r"(r[1]), "=r"(r[2]), "=r"(r[3]) : "r"(addr));
}
__device__ __forceinline__ void ldmat_x4_t(uint32_t* r, uint32_t addr) {
    asm volatile("ldmatrix.sync.aligned.m8n8.x4.trans.shared.b16 {%0,%1,%2,%3}, [%4];"
                 : "=r"(r[0]), "=r"(r[1]), "=r"(r[2]), "=r"(r[3]) : "r"(addr));
}
// fp16 inputs, fp32 accumulator (main hi*hi term)
__device__ __forceinline__ void mma_f32acc(float* c, const uint32_t* a, uint32_t b0, uint32_t b1) {
    asm volatile(
        "mma.sync.aligned.m16n8k16.row.col.f32.f16.f16.f32 "
        "{%0,%1,%2,%3}, {%4,%5,%6,%7}, {%8,%9}, {%0,%1,%2,%3};"
        : "+f"(c[0]), "+f"(c[1]), "+f"(c[2]), "+f"(c[3])
        : "r"(a[0]), "r"(a[1]), "r"(a[2]), "r"(a[3]), "r"(b0), "r"(b1));
}
// fp16 inputs, fp16 accumulator (cross terms; magnitudes ~2^-11 of main)
__device__ __forceinline__ void mma_f16acc(uint32_t* c, const uint32_t* a, uint32_t b0, uint32_t b1) {
    asm volatile(
        "mma.sync.aligned.m16n8k16.row.col.f16.f16.f16.f16 "
        "{%0,%1}, {%2,%3,%4,%5}, {%6,%7}, {%0,%1};"
        : "+r"(c[0]), "+r"(c[1])
        : "r"(a[0]), "r"(a[1]), "r"(a[2]), "r"(a[3]), "r"(b0), "r"(b1));
}
__device__ __forceinline__ void fsplit(float v, f16& h, f16& l) {
    h = __float2half_rn(v);
    l = __float2half_rn(v - __half2float(h));
}

// ---------------------------------------------------------------------------
// mma.sync GEMM, fp16 split:
//   TERMS=3: Ah*Bh (f32acc) + Ah*Bl + Al*Bh (f16acc)
//   TERMS=2: Ah*Bh (f32acc) + Ah*Bl (f16acc)  — A lo plane not loaded at all
//   BTRANS=0: B is [N,K] row-major -> C = A @ B^T
//   BTRANS=1: B is [K,N] row-major -> C = A @ B
// EPI=0: fp32 C (+bias, optional row scatter). EPI=1: f16 hi(/lo if Cl) C.
// mb/nb/kb: per-batch device tile/K bounds.
// ---------------------------------------------------------------------------
template <int EPI, int BTRANS, int TERMS>
__global__ __launch_bounds__(256, 1) void gemm_mma(
    const f16* __restrict__ Agh, const f16* __restrict__ Agl,
    const f16* __restrict__ Bgh, const f16* __restrict__ Bgl,
    const float* __restrict__ bias,
    float* __restrict__ C, f16* __restrict__ Ch, f16* __restrict__ Cl,
    int M, int N, int K,
    long long sA, long long sB, long long sC,
    const int* __restrict__ mb, const int* __restrict__ nb, const int* __restrict__ kb,
    const int* __restrict__ scat, const int* __restrict__ scnt)
{
    constexpr uint32_t BPART = BTRANS ? MATBT_BYTES : MATB_BYTES;
    constexpr uint32_t APL = (TERMS == 3) ? 2u : 1u;
    constexpr uint32_t STAGE = APL * MATA_BYTES + 2 * BPART;

    extern __shared__ char smem[];
    const int tid = threadIdx.x;
    const int wid = tid >> 5;
    const int lane = tid & 31;
    const int bz = blockIdx.z;

    const int row0 = blockIdx.y * BM;
    const int col0 = blockIdx.x * BN;
    if (mb && row0 >= mb[bz]) return;
    if (nb && col0 >= nb[bz]) return;
    const int NS = (kb ? kb[bz] : K) / BK;

    Agh += bz * sA;
    if (TERMS == 3) Agl += bz * sA;
    Bgh += bz * sB; Bgl += bz * sB;
    const long long coff = bz * sC;
    const uint32_t smem_base = smem_u32(smem);

    const int wm = (wid >> 2) * 64;   // warp m offset in tile
    const int wn = (wid & 3) * 32;    // warp n offset in tile

    float acc[4][4][4];
    uint32_t accx[4][4][2];           // f16x2 cross accumulators
#pragma unroll
    for (int i = 0; i < 4; i++)
#pragma unroll
        for (int j = 0; j < 4; j++) {
#pragma unroll
            for (int t = 0; t < 4; t++) acc[i][j][t] = 0.f;
            accx[i][j][0] = 0u; accx[i][j][1] = 0u;
        }

    auto load_stage = [&](int st, int k0) {
        const uint32_t base = smem_base + (uint32_t)st * STAGE;
#pragma unroll
        for (int i = 0; i < 2; i++) {              // A: 128 rows x 4 chunks
            int idx = tid + i * 256;
            int r = idx >> 2, c = idx & 3;
            uint32_t s = base + r * ROWB + c * 16;
            size_t g = (size_t)(row0 + r) * K + k0 + c * 8;
            cp16(s, Agh + g);
            if (TERMS == 3) cp16(s + MATA_BYTES, Agl + g);
        }
        const uint32_t bb = base + APL * MATA_BYTES;
        if (BTRANS) {
#pragma unroll
            for (int i = 0; i < 2; i++) {          // B: 32 k-rows x 16 chunks
                int idx = tid + i * 256;
                int r = idx >> 4, c = idx & 15;
                uint32_t s = bb + r * ROWB_T + c * 16;
                size_t g = (size_t)(k0 + r) * N + col0 + c * 8;
                cp16(s, Bgh + g);
                cp16(s + MATBT_BYTES, Bgl + g);
            }
        } else {
#pragma unroll
            for (int i = 0; i < 2; i++) {          // B: 128 n-rows x 4 chunks
                int idx = tid + i * 256;
                int r = idx >> 2, c = idx & 3;
                uint32_t s = bb + r * ROWB + c * 16;
                size_t g = (size_t)(col0 + r) * K + k0 + c * 8;
                cp16(s, Bgh + g);
                cp16(s + MATB_BYTES, Bgl + g);
            }
        }
        cp_commit();
    };

    const int lrow = lane & 15;
    const int lkh  = lane >> 4;
    const int brow = (lane & 7) + ((lane >> 4) << 3);
    const int bkh  = (lane >> 3) & 1;
    const int tkrow = lane & 15;
    const int tnoff = (lane >> 4) << 3;

    load_stage(0, 0);          // NS >= 4 in all uses (cntpad >= 128)
    load_stage(1, BK);
    load_stage(2, 2 * BK);

    for (int s = 0; s < NS; s++) {
        if (s < NS - 2)       cp_wait<2>();
        else if (s == NS - 2) cp_wait<1>();
        else                  cp_wait<0>();
        __syncthreads();
        if (s + 3 < NS) load_stage((s + 3) & 3, (s + 3) * BK);

        const uint32_t base = smem_base + (uint32_t)(s & 3) * STAGE;
        const uint32_t aB = base;
        const uint32_t bB = base + APL * MATA_BYTES;

#pragma unroll
        for (int ks = 0; ks < 2; ks++) {
            uint32_t afh[4][4], afl[4][4];
#pragma unroll
            for (int im = 0; im < 4; im++) {
                uint32_t ad = aB + (uint32_t)((wm + im * 16 + lrow) * ROWB + ks * 32 + lkh * 16);
                ldmat_x4(afh[im], ad);
                if (TERMS == 3) ldmat_x4(afl[im], ad + MATA_BYTES);
            }
            uint32_t bfh[2][4], bfl[2][4];
#pragma unroll
            for (int ib = 0; ib < 2; ib++) {
                if (BTRANS) {
                    uint32_t bd = bB + (uint32_t)((ks * 16 + tkrow) * ROWB_T
                                                  + ((wn + ib * 16 + tnoff) << 1));
                    ldmat_x4_t(bfh[ib], bd);
                    ldmat_x4_t(bfl[ib], bd + MATBT_BYTES);
                } else {
                    uint32_t bd = bB + (uint32_t)((wn + ib * 16 + brow) * ROWB + ks * 32 + bkh * 16);
                    ldmat_x4(bfh[ib], bd);
                    ldmat_x4(bfl[ib], bd + MATB_BYTES);
                }
            }
#pragma unroll
            for (int im = 0; im < 4; im++) {
#pragma unroll
                for (int in4 = 0; in4 < 4; in4++) {
                    const int ib = in4 >> 1, hf = (in4 & 1) * 2;
                    mma_f32acc(acc[im][in4],  afh[im], bfh[ib][hf], bfh[ib][hf + 1]);
                    mma_f16acc(accx[im][in4], afh[im], bfl[ib][hf], bfl[ib][hf + 1]);
                    if (TERMS == 3)
                        mma_f16acc(accx[im][in4], afl[im], bfh[ib][hf], bfh[ib][hf + 1]);
                }
            }
        }
        __syncthreads();
    }

    // ---- epilogue: combine f32 main + f16 cross ----
    const int lane4 = lane >> 2;
    const int lanec = (lane & 3) * 2;
#pragma unroll
    for (int im = 0; im < 4; im++) {
#pragma unroll
        for (int in4 = 0; in4 < 4; in4++) {
            const int mc = row0 + wm + im * 16 + lane4;
            const int nc = col0 + wn + in4 * 8 + lanec;
            float2 x01 = __half22float2(*(half2*)&accx[im][in4][0]);
            float2 x23 = __half22float2(*(half2*)&accx[im][in4][1]);
            float b0 = bias ? bias[nc] : 0.f;
            float b1 = bias ? bias[nc + 1] : 0.f;
            float v00 = acc[im][in4][0] + x01.x + b0, v01 = acc[im][in4][1] + x01.y + b1;
            float v10 = acc[im][in4][2] + x23.x + b0, v11 = acc[im][in4][3] + x23.y + b1;
            if (EPI == 0) {
                if (scat) {
                    const int c0 = scnt[bz];
                    if (mc < c0) {
                        int o = scat[bz * SEQ + mc];
                        *(float2*)&C[coff + (long long)o * N + nc] = make_float2(v00, v01);
                    }
                    if (mc + 8 < c0) {
                        int o = scat[bz * SEQ + mc + 8];
                        *(float2*)&C[coff + (long long)o * N + nc] = make_float2(v10, v11);
                    }
                } else {
                    *(float2*)&C[coff + (long long)mc * N + nc]       = make_float2(v00, v01);
                    *(float2*)&C[coff + (long long)(mc + 8) * N + nc] = make_float2(v10, v11);
                }
            } else {
                f16 h[2], l[2];
                fsplit(v00, h[0], l[0]); fsplit(v01, h[1], l[1]);
                *(uint32_t*)&Ch[coff + (long long)mc * N + nc] = *(uint32_t*)h;
                if (Cl) *(uint32_t*)&Cl[coff + (long long)mc * N + nc] = *(uint32_t*)l;
                fsplit(v10, h[0], l[0]); fsplit(v11, h[1], l[1]);
                *(uint32_t*)&Ch[coff + (long long)(mc + 8) * N + nc] = *(uint32_t*)h;
                if (Cl) *(uint32_t*)&Cl[coff + (long long)(mc + 8) * N + nc] = *(uint32_t*)l;
            }
        }
    }
}

// ---------------------------------------------------------------------------
// Per-batch mask compaction: deterministic inclusive scan.
// ---------------------------------------------------------------------------
__global__ __launch_bounds__(1024) void mask_scan_kernel(
    const int* __restrict__ mask, int* __restrict__ idx,
    int* __restrict__ cnt, int* __restrict__ cntpad)
{
    __shared__ int sa[2048], sb[2048];
    const int b = blockIdx.x;
    const int t = threadIdx.x;
    const int* m = mask + b * SEQ;
    sa[t] = (m[t] != 0);
    sa[t + 1024] = (m[t + 1024] != 0);
    __syncthreads();
    int* src = sa; int* dst = sb;
    for (int off = 1; off < 2048; off <<= 1) {
#pragma unroll
        for (int k = 0; k < 2; k++) {
            int i = t + k * 1024;
            dst[i] = src[i] + (i >= off ? src[i - off] : 0);
        }
        __syncthreads();
        int* tmp = src; src = dst; dst = tmp;
    }
#pragma unroll
    for (int k = 0; k < 2; k++) {
        int i = t + k * 1024;
        if (m[i] != 0) idx[b * SEQ + src[i] - 1] = i;
    }
    if (t == 0) {
        int c = src[2047];
        cnt[b] = c;
        cntpad[b] = (c + 127) & ~127;
    }
}

// ---------------------------------------------------------------------------
// Gather unmasked rows of fp32 input -> compact f16 hi/lo (zero padding rows)
// ---------------------------------------------------------------------------
__global__ __launch_bounds__(192) void gather_split_kernel(
    const float* __restrict__ in, const int* __restrict__ idx,
    const int* __restrict__ cnt, const int* __restrict__ cntpad,
    f16* __restrict__ h, f16* __restrict__ l)
{
    const int b = blockIdx.y, j = blockIdx.x;
    if (j >= cntpad[b]) return;
    const int c = threadIdx.x * 4;
    const size_t dsti = ((size_t)b * SEQ + j) * DIM + c;
    f16 hb[4], lb[4];
    if (j < cnt[b]) {
        int s = idx[b * SEQ + j];
        float4 v = *(const float4*)&in[((size_t)b * SEQ + s) * DIM + c];
        float f[4] = {v.x, v.y, v.z, v.w};
#pragma unroll
        for (int k = 0; k < 4; k++) fsplit(f[k], hb[k], lb[k]);
    } else {
#pragma unroll
        for (int k = 0; k < 4; k++) { hb[k] = __float2half_rn(0.f); lb[k] = hb[k]; }
    }
    *(uint2*)&h[dsti] = *(uint2*)hb;
    *(uint2*)&l[dsti] = *(uint2*)lb;
}

// ---------------------------------------------------------------------------
// Split 4 weight matrices in one launch
// ---------------------------------------------------------------------------
__global__ __launch_bounds__(256) void weight_split4_kernel(
    const float* __restrict__ w0, const float* __restrict__ w1,
    const float* __restrict__ w2, const float* __restrict__ w3,
    f16* __restrict__ h0, f16* __restrict__ l0, f16* __restrict__ h1, f16* __restrict__ l1,
    f16* __restrict__ h2, f16* __restrict__ l2, f16* __restrict__ h3, f16* __restrict__ l3)
{
    const int n4 = DIM * DIM / 4;
    int i = blockIdx.x * 256 + threadIdx.x;
    if (i >= n4) return;
    const float* w; f16 *h, *l;
    switch (blockIdx.y) {
        case 0: w = w0; h = h0; l = l0; break;
        case 1: w = w1; h = h1; l = l1; break;
        case 2: w = w2; h = h2; l = l2; break;
        default: w = w3; h = h3; l = l3; break;
    }
    float4 v = *(const float4*)&w[i * 4];
    float f[4] = {v.x, v.y, v.z, v.w};
    f16 hb[4], lb[4];
#pragma unroll
    for (int k = 0; k < 4; k++) fsplit(f[k], hb[k], lb[k]);
    *(uint2*)&h[i * 4] = *(uint2*)hb;
    *(uint2*)&l[i * 4] = *(uint2*)lb;
}

// ---------------------------------------------------------------------------
// Fill all output rows with fc bias (masked-query rows keep this value)
// ---------------------------------------------------------------------------
__global__ __launch_bounds__(256) void bias_fill_kernel(
    float* __restrict__ out, const float* __restrict__ bias)
{
    int i = blockIdx.x * 256 + threadIdx.x;
    int c = (i * 4) % DIM;
    *(float4*)&out[(size_t)i * 4] = *(const float4*)&bias[c];
}

// ---------------------------------------------------------------------------
// Compact softmax -> f16 P (hi only; PV keeps the V residual, not P's)
// ---------------------------------------------------------------------------
__device__ __forceinline__ float warp_max(float v) {
#pragma unroll
    for (int o = 16; o > 0; o >>= 1) v = fmaxf(v, __shfl_xor_sync(0xffffffffu, v, o));
    return v;
}
__device__ __forceinline__ float warp_sum(float v) {
#pragma unroll
    for (int o = 16; o > 0; o >>= 1) v += __shfl_xor_sync(0xffffffffu, v, o);
    return v;
}

__global__ __launch_bounds__(256) void softmax_kernel(
    const float* __restrict__ S, const int* __restrict__ cnt, const int* __restrict__ cntpad,
    f16* __restrict__ Ph)
{
    const int b = blockIdx.x >> 11;
    const int j = blockIdx.x & (SEQ - 1);
    const int cp = cntpad[b];
    if (j >= cp) return;
    const int cn = cnt[b];
    const long long row = (long long)b * SEQ + j;
    const float* __restrict__ Srow = S + row * SEQ;

    __shared__ float red_max[8];
    __shared__ float red_sum[8];
    const int tid = threadIdx.x;
    const int wid = tid >> 5, lid = tid & 31;

    float vals[8];
    float m = -INFINITY;
#pragma unroll
    for (int i = 0; i < 8; i++) {
        int c = tid + i * 256;
        float s = (c < cn) ? Srow[c] : -INFINITY;
        vals[i] = s;
        m = fmaxf(m, s);
    }
    m = warp_max(m);
    if (lid == 0) red_max[wid] = m;
    __syncthreads();
    { float t = (lid < 8) ? red_max[lid] : -INFINITY; m = warp_max(t); }

    float sum = 0.f;
#pragma unroll
    for (int i = 0; i < 8; i++) {
        float e = __expf(vals[i] - m);
        vals[i] = e;
        sum += e;
    }
    sum = warp_sum(sum);
    if (lid == 0) red_sum[wid] = sum;
    __syncthreads();
    { float t = (lid < 8) ? red_sum[lid] : 0.f; sum = warp_sum(t); }

    const float scale = (j < cn) ? (1.f / sum) : 0.f;
#pragma unroll
    for (int i = 0; i < 8; i++) {
        int c = tid + i * 256;
        if (c < cp) {
            float p = (c < cn) ? vals[i] * scale : 0.f;
            Ph[row * SEQ + c] = __float2half_rn(p);
        }
    }
}

// ---------------------------------------------------------------------------
extern "C" void kernel_launch(void* const* d_in, const int* in_sizes, int n_in,
                              void* d_out, int out_size)
{
    const float* query = (const float*)d_in[0];
    const float* value = (const float*)d_in[1];
    const int*   mask  = (const int*)  d_in[2];
    const float* q_w   = (const float*)d_in[3];
    const float* q_b   = (const float*)d_in[4];
    const float* k_w   = (const float*)d_in[5];
    const float* k_b   = (const float*)d_in[6];
    const float* v_w   = (const float*)d_in[7];
    const float* v_b   = (const float*)d_in[8];
    const float* fc_w  = (const float*)d_in[9];
    const float* fc_b  = (const float*)d_in[10];
    float* out = (float*)d_out;

    const int SMEM_KM3 = NSTAGES * (2 * MATA_BYTES + 2 * MATB_BYTES);   // 163840
    const int SMEM_KM2 = NSTAGES * (1 * MATA_BYTES + 2 * MATB_BYTES);   // 122880
    const int SMEM_TR2 = NSTAGES * (1 * MATA_BYTES + 2 * MATBT_BYTES);  // 110592
    cudaFuncSetAttribute(gemm_mma<1,0,3>, cudaFuncAttributeMaxDynamicSharedMemorySize, SMEM_KM3);
    cudaFuncSetAttribute(gemm_mma<0,0,3>, cudaFuncAttributeMaxDynamicSharedMemorySize, SMEM_KM3);
    cudaFuncSetAttribute(gemm_mma<1,0,2>, cudaFuncAttributeMaxDynamicSharedMemorySize, SMEM_KM2);
    cudaFuncSetAttribute(gemm_mma<1,1,2>, cudaFuncAttributeMaxDynamicSharedMemorySize, SMEM_TR2);
    cudaFuncSetAttribute(gemm_mma<0,0,2>, cudaFuncAttributeMaxDynamicSharedMemorySize, SMEM_KM2);

    int *idxp, *cntp, *cpp;
    f16 *xh, *xl, *yh, *yl, *wqh, *wql, *wkh, *wkl, *wvh, *wvl, *wfh, *wfl;
    f16 *qh, *ql, *kh, *kl, *vh, *vl, *ph, *mh;
    float *s_ptr;
    cudaGetSymbolAddress((void**)&idxp, g_idx);
    cudaGetSymbolAddress((void**)&cntp, g_cnt);
    cudaGetSymbolAddress((void**)&cpp, g_cntpad);
    cudaGetSymbolAddress((void**)&xh, g_xh);   cudaGetSymbolAddress((void**)&xl, g_xl);
    cudaGetSymbolAddress((void**)&yh, g_yh);   cudaGetSymbolAddress((void**)&yl, g_yl);
    cudaGetSymbolAddress((void**)&wqh, g_wqh); cudaGetSymbolAddress((void**)&wql, g_wql);
    cudaGetSymbolAddress((void**)&wkh, g_wkh); cudaGetSymbolAddress((void**)&wkl, g_wkl);
    cudaGetSymbolAddress((void**)&wvh, g_wvh); cudaGetSymbolAddress((void**)&wvl, g_wvl);
    cudaGetSymbolAddress((void**)&wfh, g_wfh); cudaGetSymbolAddress((void**)&wfl, g_wfl);
    cudaGetSymbolAddress((void**)&qh, g_qh);   cudaGetSymbolAddress((void**)&ql, g_ql);
    cudaGetSymbolAddress((void**)&kh, g_kh);   cudaGetSymbolAddress((void**)&kl, g_kl);
    cudaGetSymbolAddress((void**)&vh, g_vh);   cudaGetSymbolAddress((void**)&vl, g_vl);
    cudaGetSymbolAddress((void**)&s_ptr, g_s);
    cudaGetSymbolAddress((void**)&ph, g_ph);
    cudaGetSymbolAddress((void**)&mh, g_mh);

    // 1) mask compaction
    mask_scan_kernel<<<BATCH, 1024>>>(mask, idxp, cntp, cpp);

    // 2) gather + split inputs (compact rows); split weights (1 launch)
    {
        dim3 gg(SEQ, BATCH);
        gather_split_kernel<<<gg, 192>>>(query, idxp, cntp, cpp, xh, xl);
        gather_split_kernel<<<gg, 192>>>(value, idxp, cntp, cpp, yh, yl);
        weight_split4_kernel<<<dim3(576, 4), 256>>>(q_w, k_w, v_w, fc_w,
                                                    wqh, wql, wkh, wkl, wvh, wvl, wfh, wfl);
    }

    // 3) pre-fill output with fc bias (covers masked-query rows)
    bias_fill_kernel<<<MTOT * DIM / 4 / 256, 256>>>(out, fc_b);

    // 4) projections on compact rows (per-batch M bound)
    {
        dim3 grid(DIM / BN, SEQ / BM, BATCH);
        const long long sa = (long long)SEQ * DIM;
        // Q, K: 3-term (feed softmax; |score|~9 amplifies their error)
        gemm_mma<1,0,3><<<grid, 256, SMEM_KM3>>>(xh, xl, wqh, wql, q_b, nullptr, qh, ql,
                                                 SEQ, DIM, DIM, sa, 0, sa,
                                                 cpp, nullptr, nullptr, nullptr, nullptr);
        gemm_mma<1,0,3><<<grid, 256, SMEM_KM3>>>(yh, yl, wkh, wkl, k_b, nullptr, kh, kl,
                                                 SEQ, DIM, DIM, sa, 0, sa,
                                                 cpp, nullptr, nullptr, nullptr, nullptr);
        // V: 2-term (linear path), keeps weight residual; writes V hi+lo
        gemm_mma<1,0,2><<<grid, 256, SMEM_KM2>>>(yh, nullptr, wvh, wvl, v_b, nullptr, vh, vl,
                                                 SEQ, DIM, DIM, sa, 0, sa,
                                                 cpp, nullptr, nullptr, nullptr, nullptr);
    }

    // 5) scores (compact M and N), 3-term
    {
        dim3 grid(SEQ / BN, SEQ / BM, BATCH);
        gemm_mma<0,0,3><<<grid, 256, SMEM_KM3>>>(qh, ql, kh, kl, nullptr, s_ptr, nullptr, nullptr,
                                                 SEQ, SEQ, DIM,
                                                 (long long)SEQ * DIM, (long long)SEQ * DIM,
                                                 (long long)SEQ * SEQ,
                                                 cpp, cpp, nullptr, nullptr, nullptr);
    }

    // 6) compact softmax -> P hi
    softmax_kernel<<<BATCH * SEQ, 256>>>(s_ptr, cntp, cpp, ph);

    // 7) merged = P @ V, 2-term (A=P hi; B=V hi/lo via trans); write merged hi only
    {
        dim3 grid(DIM / BN, SEQ / BM, BATCH);
        gemm_mma<1,1,2><<<grid, 256, SMEM_TR2>>>(ph, nullptr, vh, vl, nullptr, nullptr, mh, nullptr,
                                                 SEQ, DIM, SEQ,
                                                 (long long)SEQ * SEQ, (long long)SEQ * DIM,
                                                 (long long)SEQ * DIM,
                                                 cpp, nullptr, cpp, nullptr, nullptr);
    }

    // 8) out = scatter(fc(merged)) + fc_b, 2-term (A=merged hi; B=Wf hi/lo)
    {
        dim3 grid(DIM / BN, SEQ / BM, BATCH);
        gemm_mma<0,0,2><<<grid, 256, SMEM_KM2>>>(mh, nullptr, wfh, wfl, fc_b, out, nullptr, nullptr,
                                                 SEQ, DIM, DIM,
                                                 (long long)SEQ * DIM, 0, (long long)SEQ * DIM,
                                                 cpp, nullptr, nullptr, idxp, cntp);
    }
}